// round 11
// baseline (speedup 1.0000x reference)
#include <cuda_runtime.h>
#include <cstdint>

// ---------------------------------------------------------------------------
// fused: out = relu(x@Wc^T + mean_k(x[nh])@Wn^T + mean_k(e)@We^T)
// mma.sync m16n8k8 tf32; M=64 rows/tile, N=128, K=320 = [x|mean x[nh]|mean e]
// 2 CTAs/SM (111KB SMEM each), 512 thr/CTA. ij int32. Streaming e/ij/out.
// R11: (1) 3-buffer distance-2 W prefetch -> W LDG latency fully hidden
//      (2) A-build row-pair interleave -> gather MLP 16 -> 32 per warp
// ---------------------------------------------------------------------------

#define FULLMASK 0xFFFFFFFFu

static constexpr int NR     = 100000;
static constexpr int TM     = 64;                   // rows per tile
static constexpr int NTILES = (NR + TM - 1) / TM;   // 1563
static constexpr int AS     = 324;                  // A smem stride (floats)
static constexpr int WS     = 20;                   // W chunk stride (floats)
static constexpr int KCH    = 16;                   // K per W chunk
static constexpr int NCH    = 20;                   // 20 * 16 = 320
static constexpr int NTHR   = 512;
static constexpr unsigned A_BYTES = TM * AS * 4;        // 82944
static constexpr unsigned WBUF_B  = 128 * WS * 4;       // 10240 per buffer
static constexpr unsigned SMEM_DYN = A_BYTES + 3 * WBUF_B;  // 113664 B -> 2 CTAs/SM

static __device__ __forceinline__ uint32_t smem_u32(const void* p) {
    uint32_t a;
    asm("{ .reg .u64 t; cvta.to.shared.u64 t, %1; cvt.u32.u64 %0, t; }"
        : "=r"(a) : "l"(p));
    return a;
}

static __device__ __forceinline__ uint32_t f2tf(float f) {
    uint32_t r;
    asm("cvt.rna.tf32.f32 %0, %1;" : "=r"(r) : "f"(f));
    return r;
}

static __device__ __forceinline__ void mma8(float* c, const uint32_t* a,
                                            uint32_t b0, uint32_t b1) {
    asm volatile(
        "mma.sync.aligned.m16n8k8.row.col.f32.tf32.tf32.f32 "
        "{%0,%1,%2,%3}, {%4,%5,%6,%7}, {%8,%9}, {%0,%1,%2,%3};"
        : "+f"(c[0]), "+f"(c[1]), "+f"(c[2]), "+f"(c[3])
        : "r"(a[0]), "r"(a[1]), "r"(a[2]), "r"(a[3]), "r"(b0), "r"(b1));
}

#define LDSM_X4(r0, r1, r2, r3, addr)                                          \
    asm volatile("ldmatrix.sync.aligned.m8n8.x4.shared.b16 {%0,%1,%2,%3}, [%4];" \
                 : "=r"(r0), "=r"(r1), "=r"(r2), "=r"(r3) : "r"(addr))

// gmem source pointer for W chunk n (one float4 per thread)
static __device__ __forceinline__ const float4* wsrc(
    int n, int nrow, int k4,
    const float* __restrict__ Wc, const float* __restrict__ Wn,
    const float* __restrict__ We)
{
    const float* src; int koff; int sk;
    if (n < 8)       { src = Wc; koff = n * 16;        sk = 128; }
    else if (n < 16) { src = Wn; koff = (n - 8) * 16;  sk = 128; }
    else             { src = We; koff = (n - 16) * 16; sk = 64;  }
    return (const float4*)(src + nrow * sk + koff + k4 * 4);
}

__global__ void __launch_bounds__(NTHR, 2)
conv_block_fused(const float* __restrict__ x, const float* __restrict__ e,
                 const int* __restrict__ ij,
                 const float* __restrict__ Wc, const float* __restrict__ Wn,
                 const float* __restrict__ We, float* __restrict__ out)
{
    extern __shared__ uint32_t smem[];
    uint32_t* As = smem;                        // A tile, tf32 bits, [64][AS]
    uint32_t* Wb = smem + TM * AS;              // W buffers, 3 x [128][WS]

    const int tid  = threadIdx.x;
    const int wid  = tid >> 5;       // 0..15
    const int lane = tid & 31;
    const int gid  = lane >> 2;      // 0..7
    const int tq   = lane & 3;       // 0..3
    const int row0 = blockIdx.x * TM;

    // W gmem lane mapping: one float4 per thread per chunk
    const int nrow = tid >> 2;       // 0..127
    const int k4   = tid & 3;        // 0..3
    uint32_t* wdst_base = Wb + nrow * WS + k4 * 4;

    // issue W chunk 0/1 loads now; A-build below covers their latency
    float4 wv0 = *wsrc(0, nrow, k4, Wc, Wn, We);
    float4 wv1 = *wsrc(1, nrow, k4, Wc, Wn, We);

    // ---------------- build A tile: warp per row-pair, lane per column -----
    {
        const float inv = 1.0f / 16.0f;
        const int r0  = wid * 4;
        const int rgb = row0 + r0;

        // prefetch ij for all 4 rows of this warp (2 streamed LDGs)
        int nh01 = 0, nh23 = 0;
        {
            const int rowsel = lane >> 4;       // 0 or 1
            const int nidx   = lane & 15;
            const int ra = rgb + rowsel;
            const int rb = rgb + 2 + rowsel;
            if (ra < NR) nh01 = __ldcs(ij + ra * 32 + nidx * 2);
            if (rb < NR) nh23 = __ldcs(ij + rb * 32 + nidx * 2);
        }

        #pragma unroll 1
        for (int rp = 0; rp < 2; rp++) {
            const int ra = r0 + rp * 2;         // first row of pair
            const int rga = row0 + ra;
            const int rgbr = rga + 1;
            const bool va = (rga < NR);
            const bool vb = (rgbr < NR);
            const int nsrc = rp ? nh23 : nh01;

            float4 xva = make_float4(0.f,0.f,0.f,0.f), xvb = xva;
            float4 acA = xva, acB = xva;
            if (va) xva = *(const float4*)(x + rga  * 128 + lane * 4);
            if (vb) xvb = *(const float4*)(x + rgbr * 128 + lane * 4);

            // interleaved gathers for both rows: MLP up to 32
            #pragma unroll
            for (int k = 0; k < 16; k++) {
                const int rka = __shfl_sync(FULLMASK, nsrc, k);
                const int rkb = __shfl_sync(FULLMASK, nsrc, 16 + k);
                if (va) {
                    const float4 t = *(const float4*)(x + rka * 128 + lane * 4);
                    acA.x += t.x; acA.y += t.y; acA.z += t.z; acA.w += t.w;
                }
                if (vb) {
                    const float4 t = *(const float4*)(x + rkb * 128 + lane * 4);
                    acB.x += t.x; acB.y += t.y; acB.z += t.z; acB.w += t.w;
                }
            }
            acA.x *= inv; acA.y *= inv; acA.z *= inv; acA.w *= inv;
            acB.x *= inv; acB.y *= inv; acB.z *= inv; acB.w *= inv;

            uint32_t* p;
            p = As + ra * AS + lane * 4;
            p[0]=f2tf(xva.x); p[1]=f2tf(xva.y); p[2]=f2tf(xva.z); p[3]=f2tf(xva.w);
            p = As + (ra+1) * AS + lane * 4;
            p[0]=f2tf(xvb.x); p[1]=f2tf(xvb.y); p[2]=f2tf(xvb.z); p[3]=f2tf(xvb.w);
            p = As + ra * AS + 128 + lane * 4;
            p[0]=f2tf(acA.x); p[1]=f2tf(acA.y); p[2]=f2tf(acA.z); p[3]=f2tf(acA.w);
            p = As + (ra+1) * AS + 128 + lane * 4;
            p[0]=f2tf(acB.x); p[1]=f2tf(acB.y); p[2]=f2tf(acB.z); p[3]=f2tf(acB.w);

            // e means for both rows, interleaved streams
            float2 eaA = make_float2(0.f,0.f), eaB = eaA;
            {
                const float2* epa = (const float2*)(e + (long long)rga  * 1024 + lane * 2);
                const float2* epb = (const float2*)(e + (long long)rgbr * 1024 + lane * 2);
                #pragma unroll
                for (int k = 0; k < 16; k++) {
                    if (va) { const float2 t = __ldcs(epa + k * 32); eaA.x += t.x; eaA.y += t.y; }
                    if (vb) { const float2 t = __ldcs(epb + k * 32); eaB.x += t.x; eaB.y += t.y; }
                }
            }
            eaA.x *= inv; eaA.y *= inv; eaB.x *= inv; eaB.y *= inv;
            p = As + ra * AS + 256 + lane * 2;
            p[0]=f2tf(eaA.x); p[1]=f2tf(eaA.y);
            p = As + (ra+1) * AS + 256 + lane * 2;
            p[0]=f2tf(eaB.x); p[1]=f2tf(eaB.y);
        }
    }

    // ---------------- GEMM: mma.sync tf32, warp tile 16(M) x 32(N) --------
    const int m0 = (wid & 3) * 16;
    const int n0 = (wid >> 2) * 32;

    const uint32_t sb  = smem_u32(smem);
    const uint32_t Wsb = sb + A_BYTES;
    const int t8 = lane >> 3;        // tile index 0..3
    const int w8 = lane & 7;         // row within tile
    const uint32_t a_lane = sb +
        (((m0 + (t8 & 1) * 8 + w8) * AS) + (t8 >> 1) * 4) * 4;
    const uint32_t b_lane1 = Wsb +
        (((n0 + (t8 >> 1) * 8 + w8) * WS) + (t8 & 1) * 4) * 4;
    const uint32_t b_lane2 = b_lane1 + 16 * WS * 4;   // j+2

    float acc[4][4];
    #pragma unroll
    for (int j = 0; j < 4; j++)
        #pragma unroll
        for (int q = 0; q < 4; q++) acc[j][q] = 0.f;

    // fill buffers 0/1, launch chunk-2 load (arrives during chunk 0 compute)
    {
        uint32_t* d = wdst_base;
        d[0]=f2tf(wv0.x); d[1]=f2tf(wv0.y); d[2]=f2tf(wv0.z); d[3]=f2tf(wv0.w);
        d = wdst_base + (WBUF_B / 4);
        d[0]=f2tf(wv1.x); d[1]=f2tf(wv1.y); d[2]=f2tf(wv1.z); d[3]=f2tf(wv1.w);
    }
    float4 wvn = *wsrc(2, nrow, k4, Wc, Wn, We);
    __syncthreads();   // A tile + W chunks 0,1 ready

    int bsel = 0;      // buffer of current chunk c
    int ssel = 2;      // buffer for chunk c+2
    #pragma unroll 1
    for (int c = 0; c < NCH; c++) {
        // store arrived chunk c+2, then launch load of chunk c+3
        if (c + 2 < NCH) {
            uint32_t* d = wdst_base + ssel * (WBUF_B / 4);
            d[0]=f2tf(wvn.x); d[1]=f2tf(wvn.y); d[2]=f2tf(wvn.z); d[3]=f2tf(wvn.w);
        }
        if (c + 3 < NCH) wvn = *wsrc(c + 3, nrow, k4, Wc, Wn, We);

        // compute 2 ksteps of chunk c
        const uint32_t abase = a_lane + (uint32_t)(c * KCH * 4);
        const uint32_t wbase = (uint32_t)(bsel * (int)WBUF_B);
        #pragma unroll
        for (int s = 0; s < 2; s++) {
            uint32_t a[4], b0, b1, b2, b3, b4, b5, b6, b7;
            LDSM_X4(a[0], a[1], a[2], a[3], abase + s * 32);
            LDSM_X4(b0, b1, b2, b3, b_lane1 + wbase + s * 32);
            LDSM_X4(b4, b5, b6, b7, b_lane2 + wbase + s * 32);
            mma8(acc[0], a, b0, b1);
            mma8(acc[1], a, b2, b3);
            mma8(acc[2], a, b4, b5);
            mma8(acc[3], a, b6, b7);
        }
        bsel = (bsel == 2) ? 0 : bsel + 1;
        ssel = (ssel == 2) ? 0 : ssel + 1;
        __syncthreads();
    }

    // ---------------- epilogue: relu + store (write-once: streaming) ------
    {
        const int rg0 = row0 + m0 + gid;
        const int rg1 = rg0 + 8;
        #pragma unroll
        for (int j = 0; j < 4; j++) {
            const int col = n0 + j * 8 + tq * 2;
            if (rg0 < NR) {
                float2 v;
                v.x = fmaxf(acc[j][0], 0.f);
                v.y = fmaxf(acc[j][1], 0.f);
                __stcs((float2*)(out + rg0 * 128 + col), v);
            }
            if (rg1 < NR) {
                float2 v;
                v.x = fmaxf(acc[j][2], 0.f);
                v.y = fmaxf(acc[j][3], 0.f);
                __stcs((float2*)(out + rg1 * 128 + col), v);
            }
        }
    }
}

extern "C" void kernel_launch(void* const* d_in, const int* in_sizes, int n_in,
                              void* d_out, int out_size)
{
    (void)in_sizes; (void)n_in; (void)out_size;
    const float* x  = (const float*)d_in[0];
    const float* e  = (const float*)d_in[1];
    const int*   ij = (const int*)d_in[2];
    const float* Wc = (const float*)d_in[3];
    const float* Wn = (const float*)d_in[4];
    const float* We = (const float*)d_in[5];

    cudaFuncSetAttribute(conv_block_fused,
                         cudaFuncAttributeMaxDynamicSharedMemorySize, SMEM_DYN);
    conv_block_fused<<<NTILES, NTHR, SMEM_DYN>>>(x, e, ij, Wc, Wn, We, (float*)d_out);
}

// round 12
// speedup vs baseline: 1.3380x; 1.3380x over previous
#include <cuda_runtime.h>
#include <cstdint>

// ---------------------------------------------------------------------------
// fused: out = relu(x@Wc^T + mean_k(x[nh])@Wn^T + mean_k(e)@We^T)
// mma.sync m16n8k8 tf32; M=64 rows/tile, N=128, K=320 = [x|mean x[nh]|mean e]
// 2 CTAs/SM (111KB SMEM each), 512 thr/CTA. ij int32. Streaming e/ij/out.
// R12: revert A-build to R10 batched-gather form (precomputed rk[16] -> MLP 16;
//      R11's in-loop shuffles serialized the gathers and regressed 35%).
//      Keep ONLY the 3-buffer distance-2 W prefetch pipeline from R11.
// ---------------------------------------------------------------------------

#define FULLMASK 0xFFFFFFFFu

static constexpr int NR     = 100000;
static constexpr int TM     = 64;                   // rows per tile
static constexpr int NTILES = (NR + TM - 1) / TM;   // 1563
static constexpr int AS     = 324;                  // A smem stride (floats)
static constexpr int WS     = 20;                   // W chunk stride (floats)
static constexpr int KCH    = 16;                   // K per W chunk
static constexpr int NCH    = 20;                   // 20 * 16 = 320
static constexpr int NTHR   = 512;
static constexpr unsigned A_BYTES = TM * AS * 4;        // 82944
static constexpr unsigned WBUF_B  = 128 * WS * 4;       // 10240 per buffer
static constexpr unsigned SMEM_DYN = A_BYTES + 3 * WBUF_B;  // 113664 B -> 2 CTAs/SM

static __device__ __forceinline__ uint32_t smem_u32(const void* p) {
    uint32_t a;
    asm("{ .reg .u64 t; cvta.to.shared.u64 t, %1; cvt.u32.u64 %0, t; }"
        : "=r"(a) : "l"(p));
    return a;
}

static __device__ __forceinline__ uint32_t f2tf(float f) {
    uint32_t r;
    asm("cvt.rna.tf32.f32 %0, %1;" : "=r"(r) : "f"(f));
    return r;
}

static __device__ __forceinline__ void mma8(float* c, const uint32_t* a,
                                            uint32_t b0, uint32_t b1) {
    asm volatile(
        "mma.sync.aligned.m16n8k8.row.col.f32.tf32.tf32.f32 "
        "{%0,%1,%2,%3}, {%4,%5,%6,%7}, {%8,%9}, {%0,%1,%2,%3};"
        : "+f"(c[0]), "+f"(c[1]), "+f"(c[2]), "+f"(c[3])
        : "r"(a[0]), "r"(a[1]), "r"(a[2]), "r"(a[3]), "r"(b0), "r"(b1));
}

#define LDSM_X4(r0, r1, r2, r3, addr)                                          \
    asm volatile("ldmatrix.sync.aligned.m8n8.x4.shared.b16 {%0,%1,%2,%3}, [%4];" \
                 : "=r"(r0), "=r"(r1), "=r"(r2), "=r"(r3) : "r"(addr))

// gmem source pointer for W chunk n (one float4 per thread)
static __device__ __forceinline__ const float4* wsrc(
    int n, int nrow, int k4,
    const float* __restrict__ Wc, const float* __restrict__ Wn,
    const float* __restrict__ We)
{
    const float* src; int koff; int sk;
    if (n < 8)       { src = Wc; koff = n * 16;        sk = 128; }
    else if (n < 16) { src = Wn; koff = (n - 8) * 16;  sk = 128; }
    else             { src = We; koff = (n - 16) * 16; sk = 64;  }
    return (const float4*)(src + nrow * sk + koff + k4 * 4);
}

__global__ void __launch_bounds__(NTHR, 2)
conv_block_fused(const float* __restrict__ x, const float* __restrict__ e,
                 const int* __restrict__ ij,
                 const float* __restrict__ Wc, const float* __restrict__ Wn,
                 const float* __restrict__ We, float* __restrict__ out)
{
    extern __shared__ uint32_t smem[];
    uint32_t* As = smem;                        // A tile, tf32 bits, [64][AS]
    uint32_t* Wb = smem + TM * AS;              // W buffers, 3 x [128][WS]

    const int tid  = threadIdx.x;
    const int wid  = tid >> 5;       // 0..15
    const int lane = tid & 31;
    const int gid  = lane >> 2;      // 0..7
    const int tq   = lane & 3;       // 0..3
    const int row0 = blockIdx.x * TM;

    // W gmem lane mapping: one float4 per thread per chunk
    const int nrow = tid >> 2;       // 0..127
    const int k4   = tid & 3;        // 0..3
    uint32_t* wdst_base = Wb + nrow * WS + k4 * 4;

    // issue W chunk 0/1 loads now; A-build below covers their latency
    float4 wv0 = *wsrc(0, nrow, k4, Wc, Wn, We);
    float4 wv1 = *wsrc(1, nrow, k4, Wc, Wn, We);

    // ---------------- build A tile: warp per row, lane per column ----------
    // (R10 form: indices precomputed into registers so ptxas batches the 16
    //  gather LDG.128s back-to-back -> MLP 16 per warp)
    {
        const float inv = 1.0f / 16.0f;
        const int r0  = wid * 4;
        const int rgb = row0 + r0;

        // prefetch ij for all 4 rows of this warp (2 streamed LDGs)
        int nh01 = 0, nh23 = 0;
        {
            const int rowsel = lane >> 4;       // 0 or 1
            const int nidx   = lane & 15;
            const int ra = rgb + rowsel;
            const int rb = rgb + 2 + rowsel;
            if (ra < NR) nh01 = __ldcs(ij + ra * 32 + nidx * 2);
            if (rb < NR) nh23 = __ldcs(ij + rb * 32 + nidx * 2);
        }

        #pragma unroll 1
        for (int rr = 0; rr < 4; rr++) {
            const int r  = r0 + rr;
            const int rg = row0 + r;
            const bool valid = (rg < NR);

            const int nsrc = (rr < 2) ? nh01 : nh23;
            int rk[16];
            #pragma unroll
            for (int k = 0; k < 16; k++)
                rk[k] = __shfl_sync(FULLMASK, nsrc, (rr & 1) * 16 + k);

            float4 xv = make_float4(0.f, 0.f, 0.f, 0.f);
            float4 ac = make_float4(0.f, 0.f, 0.f, 0.f);
            if (valid) {
                xv = *(const float4*)(x + rg * 128 + lane * 4);
                #pragma unroll
                for (int k = 0; k < 16; k++) {
                    // default caching: keep x L2-resident
                    const float4 t = *(const float4*)(x + rk[k] * 128 + lane * 4);
                    ac.x += t.x; ac.y += t.y; ac.z += t.z; ac.w += t.w;
                }
            }
            ac.x *= inv; ac.y *= inv; ac.z *= inv; ac.w *= inv;

            uint32_t* a0 = As + r * AS + lane * 4;
            a0[0] = f2tf(xv.x); a0[1] = f2tf(xv.y); a0[2] = f2tf(xv.z); a0[3] = f2tf(xv.w);
            uint32_t* a1 = As + r * AS + 128 + lane * 4;
            a1[0] = f2tf(ac.x); a1[1] = f2tf(ac.y); a1[2] = f2tf(ac.z); a1[3] = f2tf(ac.w);

            float2 ea = make_float2(0.f, 0.f);
            if (valid) {
                // e is a read-once stream: evict-first
                const float2* ep = (const float2*)(e + rg * 1024 + lane * 2);
                #pragma unroll
                for (int k = 0; k < 16; k++) {
                    const float2 t = __ldcs(ep + k * 32);
                    ea.x += t.x; ea.y += t.y;
                }
            }
            ea.x *= inv; ea.y *= inv;
            uint32_t* a2 = As + r * AS + 256 + lane * 2;
            a2[0] = f2tf(ea.x); a2[1] = f2tf(ea.y);
        }
    }

    // ---------------- GEMM: mma.sync tf32, warp tile 16(M) x 32(N) --------
    const int m0 = (wid & 3) * 16;
    const int n0 = (wid >> 2) * 32;

    const uint32_t sb  = smem_u32(smem);
    const uint32_t Wsb = sb + A_BYTES;
    const int t8 = lane >> 3;        // tile index 0..3
    const int w8 = lane & 7;         // row within tile
    const uint32_t a_lane = sb +
        (((m0 + (t8 & 1) * 8 + w8) * AS) + (t8 >> 1) * 4) * 4;
    const uint32_t b_lane1 = Wsb +
        (((n0 + (t8 >> 1) * 8 + w8) * WS) + (t8 & 1) * 4) * 4;
    const uint32_t b_lane2 = b_lane1 + 16 * WS * 4;   // j+2

    float acc[4][4];
    #pragma unroll
    for (int j = 0; j < 4; j++)
        #pragma unroll
        for (int q = 0; q < 4; q++) acc[j][q] = 0.f;

    // fill buffers 0/1, launch chunk-2 load (arrives during chunk-0 compute)
    {
        uint32_t* d = wdst_base;
        d[0]=f2tf(wv0.x); d[1]=f2tf(wv0.y); d[2]=f2tf(wv0.z); d[3]=f2tf(wv0.w);
        d = wdst_base + (WBUF_B / 4);
        d[0]=f2tf(wv1.x); d[1]=f2tf(wv1.y); d[2]=f2tf(wv1.z); d[3]=f2tf(wv1.w);
    }
    float4 wvn = *wsrc(2, nrow, k4, Wc, Wn, We);
    __syncthreads();   // A tile + W chunks 0,1 ready

    int bsel = 0;      // buffer of current chunk c
    int ssel = 2;      // buffer for chunk c+2
    #pragma unroll 1
    for (int c = 0; c < NCH; c++) {
        // store arrived chunk c+2, then launch load of chunk c+3
        if (c + 2 < NCH) {
            uint32_t* d = wdst_base + ssel * (WBUF_B / 4);
            d[0]=f2tf(wvn.x); d[1]=f2tf(wvn.y); d[2]=f2tf(wvn.z); d[3]=f2tf(wvn.w);
        }
        if (c + 3 < NCH) wvn = *wsrc(c + 3, nrow, k4, Wc, Wn, We);

        // compute 2 ksteps of chunk c
        const uint32_t abase = a_lane + (uint32_t)(c * KCH * 4);
        const uint32_t wbase = (uint32_t)(bsel * (int)WBUF_B);
        #pragma unroll
        for (int s = 0; s < 2; s++) {
            uint32_t a[4], b0, b1, b2, b3, b4, b5, b6, b7;
            LDSM_X4(a[0], a[1], a[2], a[3], abase + s * 32);
            LDSM_X4(b0, b1, b2, b3, b_lane1 + wbase + s * 32);
            LDSM_X4(b4, b5, b6, b7, b_lane2 + wbase + s * 32);
            mma8(acc[0], a, b0, b1);
            mma8(acc[1], a, b2, b3);
            mma8(acc[2], a, b4, b5);
            mma8(acc[3], a, b6, b7);
        }
        bsel = (bsel == 2) ? 0 : bsel + 1;
        ssel = (ssel == 2) ? 0 : ssel + 1;
        __syncthreads();
    }

    // ---------------- epilogue: relu + store (write-once: streaming) ------
    {
        const int rg0 = row0 + m0 + gid;
        const int rg1 = rg0 + 8;
        #pragma unroll
        for (int j = 0; j < 4; j++) {
            const int col = n0 + j * 8 + tq * 2;
            if (rg0 < NR) {
                float2 v;
                v.x = fmaxf(acc[j][0], 0.f);
                v.y = fmaxf(acc[j][1], 0.f);
                __stcs((float2*)(out + rg0 * 128 + col), v);
            }
            if (rg1 < NR) {
                float2 v;
                v.x = fmaxf(acc[j][2], 0.f);
                v.y = fmaxf(acc[j][3], 0.f);
                __stcs((float2*)(out + rg1 * 128 + col), v);
            }
        }
    }
}

extern "C" void kernel_launch(void* const* d_in, const int* in_sizes, int n_in,
                              void* d_out, int out_size)
{
    (void)in_sizes; (void)n_in; (void)out_size;
    const float* x  = (const float*)d_in[0];
    const float* e  = (const float*)d_in[1];
    const int*   ij = (const int*)d_in[2];
    const float* Wc = (const float*)d_in[3];
    const float* Wn = (const float*)d_in[4];
    const float* We = (const float*)d_in[5];

    cudaFuncSetAttribute(conv_block_fused,
                         cudaFuncAttributeMaxDynamicSharedMemorySize, SMEM_DYN);
    conv_block_fused<<<NTILES, NTHR, SMEM_DYN>>>(x, e, ij, Wc, Wn, We, (float*)d_out);
}